// round 12
// baseline (speedup 1.0000x reference)
#include <cuda_runtime.h>
#include <cuda_bf16.h>
#include <cuda_fp16.h>
#include <math.h>
#include <stdint.h>

#define Bv   4
#define Nv   256
#define CIN  256
#define CH   128
#define Wv   256
#define Hv   256
#define HW   (Wv*Hv)
#define Sv   256

// ---------------- scratch ---------------------------------------------------
__device__ float g_nf[Bv*Nv*CH];                 // score-premultiplied normalized nf
__device__ float g_pw[Bv*Nv*4];                  // (K_sat R_sat^T) @ worldR, padded
__device__ __half g_sfnh[(size_t)Bv*HW*CH];      // normalized sat features, fp16
__device__ float g_cand[Bv*Sv*Nv*2];
__device__ float g_logits[Bv*Sv];
__device__ __half g_Whl[2*128*256];              // 16*W_sat fp16 hi ([0,32768)) + lo

// ---------------- helpers ---------------------------------------------------
__device__ __forceinline__ uint32_t s2u(const void* p){
    uint32_t a;
    asm("{ .reg .u64 t; cvta.to.shared.u64 t, %1; cvt.u32.u64 %0, t; }" : "=r"(a) : "l"(p));
    return a;
}
__device__ __forceinline__ uint32_t packh2(float lo_e, float hi_e){
    uint32_t r;   // lower 16 bits <- lo_e (first in memory)
    asm("cvt.rn.f16x2.f32 %0, %1, %2;" : "=r"(r) : "f"(hi_e), "f"(lo_e));
    return r;
}
__device__ __forceinline__ void ldsm4(uint32_t* r, uint32_t addr){
    asm volatile("ldmatrix.sync.aligned.m8n8.x4.shared.b16 {%0,%1,%2,%3}, [%4];"
        : "=r"(r[0]), "=r"(r[1]), "=r"(r[2]), "=r"(r[3]) : "r"(addr));
}
__device__ __forceinline__ void ldsm4t(uint32_t* r, uint32_t addr){
    asm volatile("ldmatrix.sync.aligned.m8n8.x4.trans.shared.b16 {%0,%1,%2,%3}, [%4];"
        : "=r"(r[0]), "=r"(r[1]), "=r"(r[2]), "=r"(r[3]) : "r"(addr));
}
__device__ __forceinline__ void mma16816(float* d, const uint32_t* a, const uint32_t* b){
    asm volatile("mma.sync.aligned.m16n8k16.row.col.f32.f16.f16.f32 "
        "{%0,%1,%2,%3}, {%4,%5,%6,%7}, {%8,%9}, {%0,%1,%2,%3};"
        : "+f"(d[0]), "+f"(d[1]), "+f"(d[2]), "+f"(d[3])
        : "r"(a[0]), "r"(a[1]), "r"(a[2]), "r"(a[3]), "r"(b[0]), "r"(b[1]));
}
__device__ __forceinline__ void cpa16(uint32_t dst, const void* src){
    asm volatile("cp.async.ca.shared.global [%0], [%1], 16;" :: "r"(dst), "l"(src));
}
__device__ __forceinline__ void cpa_commit(){ asm volatile("cp.async.commit_group;"); }
__device__ __forceinline__ void cpa_wait0(){ asm volatile("cp.async.wait_group 0;" ::: "memory"); }

// ---------------- K0: 16*W_sat -> fp16 hi/lo (once) ------------------------
__global__ void k_wcvt(const float* __restrict__ Wsat) {
    int i = blockIdx.x * 256 + threadIdx.x;   // 0..32767
    float x = Wsat[i] * 16.0f;
    __half h = __float2half_rn(x);
    g_Whl[i] = h;
    g_Whl[32768 + i] = __float2half_rn(x - __half2float(h));
}

// ---------------- K1: nf = score * normalize(node_features @ Wn + bn) ------
__global__ void k_nf(const float* __restrict__ nfeat,
                     const float* __restrict__ Wn,
                     const float* __restrict__ bn,
                     const float* __restrict__ scores) {
    __shared__ float sf[8][CIN];
    __shared__ float red[8][128];
    __shared__ float sinv[8];
    int t = threadIdx.x;
    int cid = blockIdx.x;
    int b = cid >> 5;
    int n0 = (cid & 31) * 8;
    const float* src = nfeat + ((size_t)(b * Nv + n0)) * CIN;
    #pragma unroll
    for (int r = 0; r < 16; r++) {
        int idx = r * 128 + t;
        sf[idx >> 8][idx & 255] = src[idx];
    }
    __syncthreads();
    float acc[8];
    float bj = bn[t];
    #pragma unroll
    for (int i = 0; i < 8; i++) acc[i] = bj;
    for (int k = 0; k < CIN; k++) {
        float w = Wn[k * CH + t];
        #pragma unroll
        for (int i = 0; i < 8; i++) acc[i] += sf[i][k] * w;
    }
    #pragma unroll
    for (int i = 0; i < 8; i++) red[i][t] = acc[i] * acc[i];
    __syncthreads();
    if (t < 8) {
        float s = 0.f;
        for (int j = 0; j < 128; j++) s += red[t][j];
        sinv[t] = scores[b * Nv + n0 + t] / fmaxf(sqrtf(s), 1e-12f);
    }
    __syncthreads();
    #pragma unroll
    for (int i = 0; i < 8; i++)
        g_nf[(size_t)(b * Nv + n0 + i) * CH + t] = acc[i] * sinv[i];
}

// ---------------- K2: per-node projected ray endpoints ---------------------
__global__ void k_pw(const float* __restrict__ coords,
                     const float* __restrict__ depths,
                     const float* __restrict__ Kl,
                     const float* __restrict__ Rl,
                     const float* __restrict__ Ks,
                     const float* __restrict__ Rs) {
    int idx = blockIdx.x * blockDim.x + threadIdx.x;
    if (idx >= Bv * Nv) return;
    int b = idx / Nv;
    const float* K = Kl + b * 9;
    float a00=K[0],a01=K[1],a02=K[2],a10=K[3],a11=K[4],a12=K[5],a20=K[6],a21=K[7],a22=K[8];
    float c00 = a11*a22 - a12*a21, c01 = a02*a21 - a01*a22, c02 = a01*a12 - a02*a11;
    float c10 = a12*a20 - a10*a22, c11 = a00*a22 - a02*a20, c12 = a02*a10 - a00*a12;
    float c20 = a10*a21 - a11*a20, c21 = a01*a20 - a00*a21, c22 = a00*a11 - a01*a10;
    float det = a00*c00 + a01*c10 + a02*c20;
    float id = 1.0f / det;
    float u = coords[idx*2+0], v = coords[idx*2+1];
    float d = depths[idx];
    float cx = (c00*u + c01*v + c02) * id * d;
    float cy = (c10*u + c11*v + c12) * id * d;
    float cz = (c20*u + c21*v + c22) * id * d;
    const float* R = Rl + b * 9;
    float wx = R[0]*cx + R[1]*cy + R[2]*cz;
    float wy = R[3]*cx + R[4]*cy + R[5]*cz;
    float wz = R[6]*cx + R[7]*cy + R[8]*cz;
    const float* Km = Ks + b * 9;
    const float* Rm = Rs + b * 9;
    float P[9];
    #pragma unroll
    for (int i = 0; i < 3; i++)
        #pragma unroll
        for (int j = 0; j < 3; j++)
            P[i*3+j] = Km[i*3+0]*Rm[j*3+0] + Km[i*3+1]*Rm[j*3+1] + Km[i*3+2]*Rm[j*3+2];
    g_pw[idx*4+0] = P[0]*wx + P[1]*wy + P[2]*wz;
    g_pw[idx*4+1] = P[3]*wx + P[4]*wy + P[5]*wz;
    g_pw[idx*4+2] = P[6]*wx + P[7]*wy + P[8]*wz;
    g_pw[idx*4+3] = 0.f;
}

// ---------------- K3: sf_norm via mma.sync fp16 2-term, 2 CTA/SM -----------
#define A_PITCH 80
#define AHALF   10240
#define ABUF    20480
#define B_PITCH 272
#define BBUF    8704
#define OFF_A   0
#define OFF_B   40960
#define SMEM_K3 67584

__global__ __launch_bounds__(256, 2) void k_sfmma(const float* __restrict__ feat,
                                                  const float* __restrict__ bsat) {
    extern __shared__ char dsm[];
    __shared__ float s_inv[128];
    uint32_t sb = s2u(dsm);

    int t = threadIdx.x, wid = t >> 5, lane = t & 31;
    int warp_m = wid & 3, warp_n = wid >> 2;
    int b = blockIdx.y, p0 = blockIdx.x * 128;
    const float* fb = feat + (size_t)b * CIN * HW + p0;

    auto issueA = [&](int chunk, int buf){
        #pragma unroll
        for (int j = 0; j < 4; j++) {
            int u = j * 256 + t;
            int half = u >> 9, w = u & 511;
            int o = w >> 2, seg = w & 3;
            uint32_t dst = sb + OFF_A + buf * ABUF + half * AHALF + o * A_PITCH + seg * 16;
            const char* src = (const char*)g_Whl + half * 65536 + o * 512 + chunk * 64 + seg * 16;
            cpa16(dst, src);
        }
    };
    auto loadB = [&](int chunk, float4* pre){
        #pragma unroll
        for (int j = 0; j < 4; j++) {
            int idx = j * 256 + t;
            int c = idx >> 5, pxg = idx & 31;
            pre[j] = *(const float4*)(fb + (size_t)(chunk * 32 + c) * HW + pxg * 4);
        }
    };
    auto convB = [&](int buf, const float4* pre){
        #pragma unroll
        for (int j = 0; j < 4; j++) {
            int idx = j * 256 + t;
            int c = idx >> 5, pxg = idx & 31;
            float4 v = pre[j];
            uint2 u = make_uint2(packh2(v.x, v.y), packh2(v.z, v.w));
            *(uint2*)(dsm + OFF_B + buf * BBUF + c * B_PITCH + pxg * 8) = u;
        }
    };

    float4 pre[4];
    loadB(0, pre);
    issueA(0, 0);
    cpa_commit();
    cpa_wait0();
    convB(0, pre);
    __syncthreads();

    uint32_t lrow = lane & 15;
    uint32_t lsel = (lane >> 4) & 1;
    uint32_t aRow = (uint32_t)(warp_m * 32 + lrow) * A_PITCH + lsel * 16;
    uint32_t bCol = (uint32_t)(warp_n * 64 + lsel * 8) * 2;

    float acc[2][8][4];
    #pragma unroll
    for (int i = 0; i < 2; i++)
        #pragma unroll
        for (int j = 0; j < 8; j++)
            #pragma unroll
            for (int r = 0; r < 4; r++) acc[i][j][r] = 0.f;

    for (int c = 0; c < 8; c++) {
        if (c < 7) {
            loadB(c + 1, pre);
            issueA(c + 1, (c + 1) & 1);
            cpa_commit();
        }
        uint32_t abase = sb + OFF_A + (uint32_t)(c & 1) * ABUF;
        uint32_t bbase = sb + OFF_B + (uint32_t)(c & 1) * BBUF;
        #pragma unroll
        for (int ks = 0; ks < 2; ks++) {
            uint32_t ao = aRow + (uint32_t)ks * 32;
            uint32_t ah[2][4], al[2][4];
            ldsm4(ah[0], abase + ao);
            ldsm4(ah[1], abase + 16 * A_PITCH + ao);
            ldsm4(al[0], abase + AHALF + ao);
            ldsm4(al[1], abase + AHALF + 16 * A_PITCH + ao);
            #pragma unroll
            for (int nf2 = 0; nf2 < 4; nf2++) {
                uint32_t bo = (uint32_t)(ks * 16 + lrow) * B_PITCH + bCol + (uint32_t)nf2 * 32;
                uint32_t bb[4];
                ldsm4t(bb, bbase + bo);
                #pragma unroll
                for (int fm = 0; fm < 2; fm++) {
                    mma16816(acc[fm][2*nf2],     ah[fm], bb + 0);
                    mma16816(acc[fm][2*nf2],     al[fm], bb + 0);
                    mma16816(acc[fm][2*nf2 + 1], ah[fm], bb + 2);
                    mma16816(acc[fm][2*nf2 + 1], al[fm], bb + 2);
                }
            }
        }
        if (c < 7) {
            cpa_wait0();
            convB((c + 1) & 1, pre);
        }
        __syncthreads();
    }

    // ---- epilogue: stage [px][o] (scale+bias), per-px L2 norm, fp16 store --
    float* stg = (float*)dsm;          // 128 px x 132 floats (aliases A/B bufs)
    const float SC = 0.0625f;
    float bias0[2], bias1[2];
    #pragma unroll
    for (int fm = 0; fm < 2; fm++) {
        int m = warp_m * 32 + fm * 16 + (lane >> 2);
        bias0[fm] = bsat[m];
        bias1[fm] = bsat[m + 8];
    }
    #pragma unroll
    for (int fm = 0; fm < 2; fm++) {
        int m0 = warp_m * 32 + fm * 16 + (lane >> 2);
        #pragma unroll
        for (int fn = 0; fn < 8; fn++) {
            int n0 = warp_n * 64 + fn * 8 + (lane & 3) * 2;
            stg[n0 * 132 + m0]           = acc[fm][fn][0] * SC + bias0[fm];
            stg[(n0 + 1) * 132 + m0]     = acc[fm][fn][1] * SC + bias0[fm];
            stg[n0 * 132 + m0 + 8]       = acc[fm][fn][2] * SC + bias1[fm];
            stg[(n0 + 1) * 132 + m0 + 8] = acc[fm][fn][3] * SC + bias1[fm];
        }
    }
    __syncthreads();
    if (t < 128) {
        float ss = 0.f;
        #pragma unroll
        for (int o4 = 0; o4 < 32; o4++) {
            float4 v = *(const float4*)&stg[t * 132 + o4 * 4];
            ss += v.x*v.x + v.y*v.y + v.z*v.z + v.w*v.w;
        }
        s_inv[t] = 1.0f / fmaxf(sqrtf(ss), 1e-12f);
    }
    __syncthreads();
    __half* outp = g_sfnh + ((size_t)b * HW + p0) * CH;
    #pragma unroll
    for (int it = 0; it < 8; it++) {
        int idx = it * 256 + t;
        int px = idx >> 4, cg = (idx & 15) * 8;
        float inv = s_inv[px];
        float4 v0 = *(const float4*)&stg[px * 132 + cg];
        float4 v1 = *(const float4*)&stg[px * 132 + cg + 4];
        uint4 o;
        o.x = packh2(v0.x * inv, v0.y * inv);
        o.y = packh2(v0.z * inv, v0.w * inv);
        o.z = packh2(v1.x * inv, v1.y * inv);
        o.w = packh2(v1.z * inv, v1.w * inv);
        *(uint4*)(outp + (size_t)px * CH + cg) = o;
    }
}

// ---------------- K4: per-(b,s) projection + bilinear dot + logits ---------
__global__ __launch_bounds__(256) void k_sample(const float* __restrict__ Ksat,
                                                const float* __restrict__ Rsat,
                                                const float* __restrict__ tsat,
                                                const float* __restrict__ tinit,
                                                const float* __restrict__ radius) {
    int s = blockIdx.x, b = blockIdx.y;
    int t = threadIdx.x;
    int w = t >> 5, lane = t & 31;
    __shared__ float warpsum[8];
    float rx, ry, rz;
    {
        const float* Km = Ksat + b * 9;
        const float* Rm = Rsat + b * 9;
        float rad = radius[b];
        float stepx = -1.f + (float)(s & 15) * (2.f / 15.f);
        float stepy = -1.f + (float)(s >> 4) * (2.f / 15.f);
        float dx = tinit[b*3+0] + stepx * rad - tsat[b*3+0];
        float dy = tinit[b*3+1] + stepy * rad - tsat[b*3+1];
        float dz = tinit[b*3+2] - tsat[b*3+2];
        float P[9];
        #pragma unroll
        for (int i = 0; i < 3; i++)
            #pragma unroll
            for (int j = 0; j < 3; j++)
                P[i*3+j] = Km[i*3+0]*Rm[j*3+0] + Km[i*3+1]*Rm[j*3+1] + Km[i*3+2]*Rm[j*3+2];
        rx = P[0]*dx + P[1]*dy + P[2]*dz;
        ry = P[3]*dx + P[4]*dy + P[5]*dz;
        rz = P[6]*dx + P[7]*dy + P[8]*dz;
    }

    const __half* sfb = g_sfnh + (size_t)b * HW * CH;
    float lacc = 0.f;
    #pragma unroll 1
    for (int n = w; n < Nv; n += 16) {
        int n2 = n + 8;
        float4 pwA = *(const float4*)(g_pw + (b * Nv + n) * 4);
        float4 pwB = *(const float4*)(g_pw + (b * Nv + n2) * 4);
        float4 nfA = *(const float4*)(g_nf + (size_t)(b * Nv + n) * CH + lane * 4);
        float4 nfB = *(const float4*)(g_nf + (size_t)(b * Nv + n2) * CH + lane * 4);
        float wwA = pwA.z + rz, wwB = pwB.z + rz;
        float cxA = (pwA.x + rx) / wwA, cyA = (pwA.y + ry) / wwA;
        float cxB = (pwB.x + rx) / wwB, cyB = (pwB.y + ry) / wwB;
        if (lane == 0) {
            float2* cd = (float2*)(g_cand + ((size_t)(b*Sv + s) * Nv) * 2);
            cd[n]  = make_float2(cxA, cyA);
            cd[n2] = make_float2(cxB, cyB);
        }
        float pxA = ((cxA / 255.0f * 2.0f) * (float)Wv - 1.f) * 0.5f;
        float pyA = ((cyA / 255.0f * 2.0f) * (float)Hv - 1.f) * 0.5f;
        float pxB = ((cxB / 255.0f * 2.0f) * (float)Wv - 1.f) * 0.5f;
        float pyB = ((cyB / 255.0f * 2.0f) * (float)Hv - 1.f) * 0.5f;
        float x0A = floorf(pxA), y0A = floorf(pyA);
        float x0B = floorf(pxB), y0B = floorf(pyB);
        float fxA = pxA - x0A, fyA = pyA - y0A;
        float fxB = pxB - x0B, fyB = pyB - y0B;
        float cwA[4] = {(1.f-fyA)*(1.f-fxA), (1.f-fyA)*fxA, fyA*(1.f-fxA), fyA*fxA};
        float cwB[4] = {(1.f-fyB)*(1.f-fxB), (1.f-fyB)*fxB, fyB*(1.f-fxB), fyB*fxB};
        float accA = 0.f, accB = 0.f;
        #pragma unroll
        for (int cc = 0; cc < 4; cc++) {
            float xfA = x0A + (float)(cc & 1), yfA = y0A + (float)(cc >> 1);
            float xfB = x0B + (float)(cc & 1), yfB = y0B + (float)(cc >> 1);
            float mA = (xfA >= 0.f && xfA <= 255.f && yfA >= 0.f && yfA <= 255.f) ? 1.f : 0.f;
            float mB = (xfB >= 0.f && xfB <= 255.f && yfB >= 0.f && yfB <= 255.f) ? 1.f : 0.f;
            int xiA = min(max((int)xfA, 0), 255), yiA = min(max((int)yfA, 0), 255);
            int xiB = min(max((int)xfB, 0), 255), yiB = min(max((int)yfB, 0), 255);
            uint2 rA = *(const uint2*)(sfb + ((size_t)(yiA * Wv + xiA)) * CH + lane * 4);
            uint2 rB = *(const uint2*)(sfb + ((size_t)(yiB * Wv + xiB)) * CH + lane * 4);
            float2 a0 = __half22float2(*(__half2*)&rA.x);
            float2 a1 = __half22float2(*(__half2*)&rA.y);
            float2 b0 = __half22float2(*(__half2*)&rB.x);
            float2 b1 = __half22float2(*(__half2*)&rB.y);
            float dA = nfA.x*a0.x + nfA.y*a0.y + nfA.z*a1.x + nfA.w*a1.y;
            float dB = nfB.x*b0.x + nfB.y*b0.y + nfB.z*b1.x + nfB.w*b1.y;
            accA += cwA[cc] * mA * dA;
            accB += cwB[cc] * mB * dB;
        }
        lacc += accA + accB;    // scores folded into g_nf
    }
    #pragma unroll
    for (int o = 16; o > 0; o >>= 1) lacc += __shfl_down_sync(0xffffffffu, lacc, o);
    if (lane == 0) warpsum[w] = lacc;
    __syncthreads();
    if (t == 0) {
        float s8 = 0.f;
        #pragma unroll
        for (int i = 0; i < 8; i++) s8 += warpsum[i];
        g_logits[b * Sv + s] = s8;
    }
}

// ---------------- K5: softmax, argmax, outputs -----------------------------
__global__ void k_final(float* __restrict__ out,
                        const float* __restrict__ tinit,
                        const float* __restrict__ radius,
                        const float* __restrict__ lscale) {
    int b = blockIdx.x;
    int t = threadIdx.x;   // 256
    __shared__ float sred[256];
    __shared__ int bestI;
    float escale = expf(lscale[0]);
    float L = g_logits[b * Sv + t] * escale;
    sred[t] = L; __syncthreads();
    for (int o = 128; o > 0; o >>= 1) {
        if (t < o) sred[t] = fmaxf(sred[t], sred[t + o]);
        __syncthreads();
    }
    float m = sred[0];
    __syncthreads();
    float e = expf(L - m);
    sred[t] = e; __syncthreads();
    for (int o = 128; o > 0; o >>= 1) {
        if (t < o) sred[t] += sred[t + o];
        __syncthreads();
    }
    float Z = sred[0];
    out[6144 + b * Sv + t] = e / Z;
    if (t == 0) bestI = 1 << 30;
    __syncthreads();
    if (L == m) atomicMin(&bestI, t);
    __syncthreads();
    int bi = bestI;
    float mx = g_cand[((size_t)(b * Sv + bi) * Nv + t) * 2 + 0];
    float my = g_cand[((size_t)(b * Sv + bi) * Nv + t) * 2 + 1];
    out[(b * Nv + t) * 2 + 0] = mx;
    out[(b * Nv + t) * 2 + 1] = my;
    out[2048 + b * Nv + t] =
        (mx >= 0.f && mx < (float)Wv && my >= 0.f && my < (float)Hv) ? 1.f : 0.f;
    float rad = radius[b];
    float sx = -1.f + (float)(t & 15) * (2.f / 15.f);
    float sy = -1.f + (float)(t >> 4) * (2.f / 15.f);
    out[3072 + (b * Sv + t) * 3 + 0] = tinit[b*3+0] + sx * rad;
    out[3072 + (b * Sv + t) * 3 + 1] = tinit[b*3+1] + sy * rad;
    out[3072 + (b * Sv + t) * 3 + 2] = tinit[b*3+2];
}

// ---------------- launch ----------------------------------------------------
extern "C" void kernel_launch(void* const* d_in, const int* in_sizes, int n_in,
                              void* d_out, int out_size) {
    const float* node_coords   = (const float*)d_in[0];
    const float* node_scores   = (const float*)d_in[1];
    const float* node_features = (const float*)d_in[2];
    const float* node_depths   = (const float*)d_in[3];
    const float* K_left        = (const float*)d_in[4];
    const float* R_left        = (const float*)d_in[5];
    const float* t_init        = (const float*)d_in[6];
    const float* sat_featmap   = (const float*)d_in[7];
    const float* K_sat         = (const float*)d_in[8];
    const float* R_sat         = (const float*)d_in[9];
    const float* t_sat         = (const float*)d_in[10];
    const float* radius        = (const float*)d_in[11];
    int off = (n_in >= 18) ? 0 : -1;
    const float* W_node      = (const float*)d_in[13 + off];
    const float* b_node      = (const float*)d_in[14 + off];
    const float* W_sat       = (const float*)d_in[15 + off];
    const float* b_sat       = (const float*)d_in[16 + off];
    const float* logit_scale = (const float*)d_in[17 + off];
    float* out = (float*)d_out;

    cudaFuncSetAttribute(k_sfmma, cudaFuncAttributeMaxDynamicSharedMemorySize, SMEM_K3);

    k_wcvt<<<128, 256>>>(W_sat);
    k_nf<<<128, 128>>>(node_features, W_node, b_node, node_scores);
    k_pw<<<4, 256>>>(node_coords, node_depths, K_left, R_left, K_sat, R_sat);
    k_sfmma<<<dim3(512, Bv), 256, SMEM_K3>>>(sat_featmap, b_sat);
    k_sample<<<dim3(Sv, Bv), 256>>>(K_sat, R_sat, t_sat, t_init, radius);
    k_final<<<Bv, 256>>>(out, t_init, radius, logit_scale);
}

// round 13
// speedup vs baseline: 1.0395x; 1.0395x over previous
#include <cuda_runtime.h>
#include <cuda_bf16.h>
#include <cuda_fp16.h>
#include <math.h>
#include <stdint.h>

#define Bv   4
#define Nv   256
#define CIN  256
#define CH   128
#define Wv   256
#define Hv   256
#define HW   (Wv*Hv)
#define Sv   256

// ---------------- scratch ---------------------------------------------------
__device__ float g_nf[Bv*Nv*CH];                 // score-premultiplied normalized nf
__device__ float g_pw[Bv*Nv*4];                  // (K_sat R_sat^T) @ worldR, padded
__device__ __half g_sfnh[(size_t)Bv*HW*CH];      // normalized sat features, fp16
__device__ float g_cand[Bv*Sv*Nv*2];
__device__ float g_logits[Bv*Sv];
__device__ __half g_Whl[2*128*256];              // 16*W_sat fp16 hi ([0,32768)) + lo

// ---------------- helpers ---------------------------------------------------
__device__ __forceinline__ uint32_t s2u(const void* p){
    uint32_t a;
    asm("{ .reg .u64 t; cvta.to.shared.u64 t, %1; cvt.u32.u64 %0, t; }" : "=r"(a) : "l"(p));
    return a;
}
__device__ __forceinline__ uint32_t packh2(float lo_e, float hi_e){
    uint32_t r;   // lower 16 bits <- lo_e (first in memory)
    asm("cvt.rn.f16x2.f32 %0, %1, %2;" : "=r"(r) : "f"(hi_e), "f"(lo_e));
    return r;
}
__device__ __forceinline__ void ldsm4(uint32_t* r, uint32_t addr){
    asm volatile("ldmatrix.sync.aligned.m8n8.x4.shared.b16 {%0,%1,%2,%3}, [%4];"
        : "=r"(r[0]), "=r"(r[1]), "=r"(r[2]), "=r"(r[3]) : "r"(addr));
}
__device__ __forceinline__ void ldsm4t(uint32_t* r, uint32_t addr){
    asm volatile("ldmatrix.sync.aligned.m8n8.x4.trans.shared.b16 {%0,%1,%2,%3}, [%4];"
        : "=r"(r[0]), "=r"(r[1]), "=r"(r[2]), "=r"(r[3]) : "r"(addr));
}
__device__ __forceinline__ void mma16816(float* d, const uint32_t* a, const uint32_t* b){
    asm volatile("mma.sync.aligned.m16n8k16.row.col.f32.f16.f16.f32 "
        "{%0,%1,%2,%3}, {%4,%5,%6,%7}, {%8,%9}, {%0,%1,%2,%3};"
        : "+f"(d[0]), "+f"(d[1]), "+f"(d[2]), "+f"(d[3])
        : "r"(a[0]), "r"(a[1]), "r"(a[2]), "r"(a[3]), "r"(b[0]), "r"(b[1]));
}
__device__ __forceinline__ void cpa16(uint32_t dst, const void* src){
    asm volatile("cp.async.ca.shared.global [%0], [%1], 16;" :: "r"(dst), "l"(src));
}
__device__ __forceinline__ void cpa_commit(){ asm volatile("cp.async.commit_group;"); }
__device__ __forceinline__ void cpa_wait0(){ asm volatile("cp.async.wait_group 0;" ::: "memory"); }

// ---------------- K0: 16*W_sat -> fp16 hi/lo (once) ------------------------
__global__ void k_wcvt(const float* __restrict__ Wsat) {
    int i = blockIdx.x * 256 + threadIdx.x;   // 0..32767
    float x = Wsat[i] * 16.0f;
    __half h = __float2half_rn(x);
    g_Whl[i] = h;
    g_Whl[32768 + i] = __float2half_rn(x - __half2float(h));
}

// ---------------- K1: nf = score * normalize(node_features @ Wn + bn) ------
__global__ void k_nf(const float* __restrict__ nfeat,
                     const float* __restrict__ Wn,
                     const float* __restrict__ bn,
                     const float* __restrict__ scores) {
    __shared__ float sf[8][CIN];
    __shared__ float red[8][128];
    __shared__ float sinv[8];
    int t = threadIdx.x;
    int cid = blockIdx.x;
    int b = cid >> 5;
    int n0 = (cid & 31) * 8;
    const float* src = nfeat + ((size_t)(b * Nv + n0)) * CIN;
    #pragma unroll
    for (int r = 0; r < 16; r++) {
        int idx = r * 128 + t;
        sf[idx >> 8][idx & 255] = src[idx];
    }
    __syncthreads();
    float acc[8];
    float bj = bn[t];
    #pragma unroll
    for (int i = 0; i < 8; i++) acc[i] = bj;
    for (int k = 0; k < CIN; k++) {
        float w = Wn[k * CH + t];
        #pragma unroll
        for (int i = 0; i < 8; i++) acc[i] += sf[i][k] * w;
    }
    #pragma unroll
    for (int i = 0; i < 8; i++) red[i][t] = acc[i] * acc[i];
    __syncthreads();
    if (t < 8) {
        float s = 0.f;
        for (int j = 0; j < 128; j++) s += red[t][j];
        sinv[t] = scores[b * Nv + n0 + t] / fmaxf(sqrtf(s), 1e-12f);
    }
    __syncthreads();
    #pragma unroll
    for (int i = 0; i < 8; i++)
        g_nf[(size_t)(b * Nv + n0 + i) * CH + t] = acc[i] * sinv[i];
}

// ---------------- K2: per-node projected ray endpoints ---------------------
__global__ void k_pw(const float* __restrict__ coords,
                     const float* __restrict__ depths,
                     const float* __restrict__ Kl,
                     const float* __restrict__ Rl,
                     const float* __restrict__ Ks,
                     const float* __restrict__ Rs) {
    int idx = blockIdx.x * blockDim.x + threadIdx.x;
    if (idx >= Bv * Nv) return;
    int b = idx / Nv;
    const float* K = Kl + b * 9;
    float a00=K[0],a01=K[1],a02=K[2],a10=K[3],a11=K[4],a12=K[5],a20=K[6],a21=K[7],a22=K[8];
    float c00 = a11*a22 - a12*a21, c01 = a02*a21 - a01*a22, c02 = a01*a12 - a02*a11;
    float c10 = a12*a20 - a10*a22, c11 = a00*a22 - a02*a20, c12 = a02*a10 - a00*a12;
    float c20 = a10*a21 - a11*a20, c21 = a01*a20 - a00*a21, c22 = a00*a11 - a01*a10;
    float det = a00*c00 + a01*c10 + a02*c20;
    float id = 1.0f / det;
    float u = coords[idx*2+0], v = coords[idx*2+1];
    float d = depths[idx];
    float cx = (c00*u + c01*v + c02) * id * d;
    float cy = (c10*u + c11*v + c12) * id * d;
    float cz = (c20*u + c21*v + c22) * id * d;
    const float* R = Rl + b * 9;
    float wx = R[0]*cx + R[1]*cy + R[2]*cz;
    float wy = R[3]*cx + R[4]*cy + R[5]*cz;
    float wz = R[6]*cx + R[7]*cy + R[8]*cz;
    const float* Km = Ks + b * 9;
    const float* Rm = Rs + b * 9;
    float P[9];
    #pragma unroll
    for (int i = 0; i < 3; i++)
        #pragma unroll
        for (int j = 0; j < 3; j++)
            P[i*3+j] = Km[i*3+0]*Rm[j*3+0] + Km[i*3+1]*Rm[j*3+1] + Km[i*3+2]*Rm[j*3+2];
    g_pw[idx*4+0] = P[0]*wx + P[1]*wy + P[2]*wz;
    g_pw[idx*4+1] = P[3]*wx + P[4]*wy + P[5]*wz;
    g_pw[idx*4+2] = P[6]*wx + P[7]*wy + P[8]*wz;
    g_pw[idx*4+3] = 0.f;
}

// ---------------- K3: sf_norm via mma.sync fp16 2-term, 2 CTA/SM -----------
#define A_PITCH 80
#define AHALF   10240
#define ABUF    20480
#define B_PITCH 272
#define BBUF    8704
#define OFF_A   0
#define OFF_B   40960
#define SMEM_K3 67584

__global__ __launch_bounds__(256, 2) void k_sfmma(const float* __restrict__ feat,
                                                  const float* __restrict__ bsat) {
    extern __shared__ char dsm[];
    __shared__ float s_inv[128];
    uint32_t sb = s2u(dsm);

    int t = threadIdx.x, wid = t >> 5, lane = t & 31;
    int warp_m = wid & 3, warp_n = wid >> 2;
    int b = blockIdx.y, p0 = blockIdx.x * 128;
    const float* fb = feat + (size_t)b * CIN * HW + p0;

    auto issueA = [&](int chunk, int buf){
        #pragma unroll
        for (int j = 0; j < 4; j++) {
            int u = j * 256 + t;
            int half = u >> 9, w = u & 511;
            int o = w >> 2, seg = w & 3;
            uint32_t dst = sb + OFF_A + buf * ABUF + half * AHALF + o * A_PITCH + seg * 16;
            const char* src = (const char*)g_Whl + half * 65536 + o * 512 + chunk * 64 + seg * 16;
            cpa16(dst, src);
        }
    };
    auto loadB = [&](int chunk, float4* pre){
        #pragma unroll
        for (int j = 0; j < 4; j++) {
            int idx = j * 256 + t;
            int c = idx >> 5, pxg = idx & 31;
            pre[j] = *(const float4*)(fb + (size_t)(chunk * 32 + c) * HW + pxg * 4);
        }
    };
    auto convB = [&](int buf, const float4* pre){
        #pragma unroll
        for (int j = 0; j < 4; j++) {
            int idx = j * 256 + t;
            int c = idx >> 5, pxg = idx & 31;
            float4 v = pre[j];
            uint2 u = make_uint2(packh2(v.x, v.y), packh2(v.z, v.w));
            *(uint2*)(dsm + OFF_B + buf * BBUF + c * B_PITCH + pxg * 8) = u;
        }
    };

    float4 pre[4];
    loadB(0, pre);
    issueA(0, 0);
    cpa_commit();
    cpa_wait0();
    convB(0, pre);
    __syncthreads();

    uint32_t lrow = lane & 15;
    uint32_t lsel = (lane >> 4) & 1;
    uint32_t aRow = (uint32_t)(warp_m * 32 + lrow) * A_PITCH + lsel * 16;
    uint32_t bCol = (uint32_t)(warp_n * 64 + lsel * 8) * 2;

    float acc[2][8][4];
    #pragma unroll
    for (int i = 0; i < 2; i++)
        #pragma unroll
        for (int j = 0; j < 8; j++)
            #pragma unroll
            for (int r = 0; r < 4; r++) acc[i][j][r] = 0.f;

    for (int c = 0; c < 8; c++) {
        if (c < 7) {
            loadB(c + 1, pre);
            issueA(c + 1, (c + 1) & 1);
            cpa_commit();
        }
        uint32_t abase = sb + OFF_A + (uint32_t)(c & 1) * ABUF;
        uint32_t bbase = sb + OFF_B + (uint32_t)(c & 1) * BBUF;
        #pragma unroll
        for (int ks = 0; ks < 2; ks++) {
            uint32_t ao = aRow + (uint32_t)ks * 32;
            // hoisted operand loads: all A (hi+lo) and all 4 B tiles
            uint32_t ah[2][4], al[2][4], bb[4][4];
            ldsm4(ah[0], abase + ao);
            ldsm4(ah[1], abase + 16 * A_PITCH + ao);
            ldsm4(al[0], abase + AHALF + ao);
            ldsm4(al[1], abase + AHALF + 16 * A_PITCH + ao);
            #pragma unroll
            for (int nf2 = 0; nf2 < 4; nf2++)
                ldsm4t(bb[nf2], bbase + (uint32_t)(ks * 16 + lrow) * B_PITCH
                                      + bCol + (uint32_t)nf2 * 32);
            // hi sweep: 16 independent MMAs
            #pragma unroll
            for (int nf2 = 0; nf2 < 4; nf2++)
                #pragma unroll
                for (int fm = 0; fm < 2; fm++) {
                    mma16816(acc[fm][2*nf2],     ah[fm], bb[nf2] + 0);
                    mma16816(acc[fm][2*nf2 + 1], ah[fm], bb[nf2] + 2);
                }
            // lo sweep: 16 independent MMAs (RAW pairs spaced 16 apart)
            #pragma unroll
            for (int nf2 = 0; nf2 < 4; nf2++)
                #pragma unroll
                for (int fm = 0; fm < 2; fm++) {
                    mma16816(acc[fm][2*nf2],     al[fm], bb[nf2] + 0);
                    mma16816(acc[fm][2*nf2 + 1], al[fm], bb[nf2] + 2);
                }
        }
        if (c < 7) {
            cpa_wait0();
            convB((c + 1) & 1, pre);
        }
        __syncthreads();
    }

    // ---- epilogue: stage [px][o] (scale+bias), per-px L2 norm, fp16 store --
    float* stg = (float*)dsm;          // 128 px x 132 floats (aliases A/B bufs)
    const float SC = 0.0625f;
    float bias0[2], bias1[2];
    #pragma unroll
    for (int fm = 0; fm < 2; fm++) {
        int m = warp_m * 32 + fm * 16 + (lane >> 2);
        bias0[fm] = bsat[m];
        bias1[fm] = bsat[m + 8];
    }
    #pragma unroll
    for (int fm = 0; fm < 2; fm++) {
        int m0 = warp_m * 32 + fm * 16 + (lane >> 2);
        #pragma unroll
        for (int fn = 0; fn < 8; fn++) {
            int n0 = warp_n * 64 + fn * 8 + (lane & 3) * 2;
            stg[n0 * 132 + m0]           = acc[fm][fn][0] * SC + bias0[fm];
            stg[(n0 + 1) * 132 + m0]     = acc[fm][fn][1] * SC + bias0[fm];
            stg[n0 * 132 + m0 + 8]       = acc[fm][fn][2] * SC + bias1[fm];
            stg[(n0 + 1) * 132 + m0 + 8] = acc[fm][fn][3] * SC + bias1[fm];
        }
    }
    __syncthreads();
    if (t < 128) {
        float ss = 0.f;
        #pragma unroll
        for (int o4 = 0; o4 < 32; o4++) {
            float4 v = *(const float4*)&stg[t * 132 + o4 * 4];
            ss += v.x*v.x + v.y*v.y + v.z*v.z + v.w*v.w;
        }
        s_inv[t] = 1.0f / fmaxf(sqrtf(ss), 1e-12f);
    }
    __syncthreads();
    __half* outp = g_sfnh + ((size_t)b * HW + p0) * CH;
    #pragma unroll
    for (int it = 0; it < 8; it++) {
        int idx = it * 256 + t;
        int px = idx >> 4, cg = (idx & 15) * 8;
        float inv = s_inv[px];
        float4 v0 = *(const float4*)&stg[px * 132 + cg];
        float4 v1 = *(const float4*)&stg[px * 132 + cg + 4];
        uint4 o;
        o.x = packh2(v0.x * inv, v0.y * inv);
        o.y = packh2(v0.z * inv, v0.w * inv);
        o.z = packh2(v1.x * inv, v1.y * inv);
        o.w = packh2(v1.z * inv, v1.w * inv);
        *(uint4*)(outp + (size_t)px * CH + cg) = o;
    }
}

// ---------------- K4: per-(b,s) projection + bilinear dot + logits ---------
__global__ __launch_bounds__(256) void k_sample(const float* __restrict__ Ksat,
                                                const float* __restrict__ Rsat,
                                                const float* __restrict__ tsat,
                                                const float* __restrict__ tinit,
                                                const float* __restrict__ radius) {
    int s = blockIdx.x, b = blockIdx.y;
    int t = threadIdx.x;
    int w = t >> 5, lane = t & 31;
    __shared__ float warpsum[8];
    float rx, ry, rz;
    {
        const float* Km = Ksat + b * 9;
        const float* Rm = Rsat + b * 9;
        float rad = radius[b];
        float stepx = -1.f + (float)(s & 15) * (2.f / 15.f);
        float stepy = -1.f + (float)(s >> 4) * (2.f / 15.f);
        float dx = tinit[b*3+0] + stepx * rad - tsat[b*3+0];
        float dy = tinit[b*3+1] + stepy * rad - tsat[b*3+1];
        float dz = tinit[b*3+2] - tsat[b*3+2];
        float P[9];
        #pragma unroll
        for (int i = 0; i < 3; i++)
            #pragma unroll
            for (int j = 0; j < 3; j++)
                P[i*3+j] = Km[i*3+0]*Rm[j*3+0] + Km[i*3+1]*Rm[j*3+1] + Km[i*3+2]*Rm[j*3+2];
        rx = P[0]*dx + P[1]*dy + P[2]*dz;
        ry = P[3]*dx + P[4]*dy + P[5]*dz;
        rz = P[6]*dx + P[7]*dy + P[8]*dz;
    }

    const float PXS = 256.0f / 255.0f;   // px = cand * PXS - 0.5
    const __half* sfb = g_sfnh + (size_t)b * HW * CH;
    float lacc = 0.f;
    #pragma unroll 1
    for (int n = w; n < Nv; n += 16) {
        int n2 = n + 8;
        float4 pwA = *(const float4*)(g_pw + (b * Nv + n) * 4);
        float4 pwB = *(const float4*)(g_pw + (b * Nv + n2) * 4);
        float4 nfA = *(const float4*)(g_nf + (size_t)(b * Nv + n) * CH + lane * 4);
        float4 nfB = *(const float4*)(g_nf + (size_t)(b * Nv + n2) * CH + lane * 4);
        float wwA = pwA.z + rz, wwB = pwB.z + rz;
        float cxA = (pwA.x + rx) / wwA, cyA = (pwA.y + ry) / wwA;
        float cxB = (pwB.x + rx) / wwB, cyB = (pwB.y + ry) / wwB;
        if (lane == 0) {
            float2* cd = (float2*)(g_cand + ((size_t)(b*Sv + s) * Nv) * 2);
            cd[n]  = make_float2(cxA, cyA);
            cd[n2] = make_float2(cxB, cyB);
        }
        float pxA = cxA * PXS - 0.5f, pyA = cyA * PXS - 0.5f;
        float pxB = cxB * PXS - 0.5f, pyB = cyB * PXS - 0.5f;
        float x0A = floorf(pxA), y0A = floorf(pyA);
        float x0B = floorf(pxB), y0B = floorf(pyB);
        float fxA = pxA - x0A, fyA = pyA - y0A;
        float fxB = pxB - x0B, fyB = pyB - y0B;
        float cwA[4] = {(1.f-fyA)*(1.f-fxA), (1.f-fyA)*fxA, fyA*(1.f-fxA), fyA*fxA};
        float cwB[4] = {(1.f-fyB)*(1.f-fxB), (1.f-fyB)*fxB, fyB*(1.f-fxB), fyB*fxB};
        float accA = 0.f, accB = 0.f;
        #pragma unroll
        for (int cc = 0; cc < 4; cc++) {
            float xfA = x0A + (float)(cc & 1), yfA = y0A + (float)(cc >> 1);
            float xfB = x0B + (float)(cc & 1), yfB = y0B + (float)(cc >> 1);
            float mA = (xfA >= 0.f && xfA <= 255.f && yfA >= 0.f && yfA <= 255.f) ? 1.f : 0.f;
            float mB = (xfB >= 0.f && xfB <= 255.f && yfB >= 0.f && yfB <= 255.f) ? 1.f : 0.f;
            int xiA = min(max((int)xfA, 0), 255), yiA = min(max((int)yfA, 0), 255);
            int xiB = min(max((int)xfB, 0), 255), yiB = min(max((int)yfB, 0), 255);
            uint2 rA = *(const uint2*)(sfb + ((size_t)(yiA * Wv + xiA)) * CH + lane * 4);
            uint2 rB = *(const uint2*)(sfb + ((size_t)(yiB * Wv + xiB)) * CH + lane * 4);
            float2 a0 = __half22float2(*(__half2*)&rA.x);
            float2 a1 = __half22float2(*(__half2*)&rA.y);
            float2 b0 = __half22float2(*(__half2*)&rB.x);
            float2 b1 = __half22float2(*(__half2*)&rB.y);
            float dA = nfA.x*a0.x + nfA.y*a0.y + nfA.z*a1.x + nfA.w*a1.y;
            float dB = nfB.x*b0.x + nfB.y*b0.y + nfB.z*b1.x + nfB.w*b1.y;
            accA += cwA[cc] * mA * dA;
            accB += cwB[cc] * mB * dB;
        }
        lacc += accA + accB;    // scores folded into g_nf
    }
    #pragma unroll
    for (int o = 16; o > 0; o >>= 1) lacc += __shfl_down_sync(0xffffffffu, lacc, o);
    if (lane == 0) warpsum[w] = lacc;
    __syncthreads();
    if (t == 0) {
        float s8 = 0.f;
        #pragma unroll
        for (int i = 0; i < 8; i++) s8 += warpsum[i];
        g_logits[b * Sv + s] = s8;
    }
}

// ---------------- K5: softmax, argmax, outputs -----------------------------
__global__ void k_final(float* __restrict__ out,
                        const float* __restrict__ tinit,
                        const float* __restrict__ radius,
                        const float* __restrict__ lscale) {
    int b = blockIdx.x;
    int t = threadIdx.x;   // 256
    __shared__ float sred[256];
    __shared__ int bestI;
    float escale = expf(lscale[0]);
    float L = g_logits[b * Sv + t] * escale;
    sred[t] = L; __syncthreads();
    for (int o = 128; o > 0; o >>= 1) {
        if (t < o) sred[t] = fmaxf(sred[t], sred[t + o]);
        __syncthreads();
    }
    float m = sred[0];
    __syncthreads();
    float e = expf(L - m);
    sred[t] = e; __syncthreads();
    for (int o = 128; o > 0; o >>= 1) {
        if (t < o) sred[t] += sred[t + o];
        __syncthreads();
    }
    float Z = sred[0];
    out[6144 + b * Sv + t] = e / Z;
    if (t == 0) bestI = 1 << 30;
    __syncthreads();
    if (L == m) atomicMin(&bestI, t);
    __syncthreads();
    int bi = bestI;
    float mx = g_cand[((size_t)(b * Sv + bi) * Nv + t) * 2 + 0];
    float my = g_cand[((size_t)(b * Sv + bi) * Nv + t) * 2 + 1];
    out[(b * Nv + t) * 2 + 0] = mx;
    out[(b * Nv + t) * 2 + 1] = my;
    out[2048 + b * Nv + t] =
        (mx >= 0.f && mx < (float)Wv && my >= 0.f && my < (float)Hv) ? 1.f : 0.f;
    float rad = radius[b];
    float sx = -1.f + (float)(t & 15) * (2.f / 15.f);
    float sy = -1.f + (float)(t >> 4) * (2.f / 15.f);
    out[3072 + (b * Sv + t) * 3 + 0] = tinit[b*3+0] + sx * rad;
    out[3072 + (b * Sv + t) * 3 + 1] = tinit[b*3+1] + sy * rad;
    out[3072 + (b * Sv + t) * 3 + 2] = tinit[b*3+2];
}

// ---------------- launch ----------------------------------------------------
extern "C" void kernel_launch(void* const* d_in, const int* in_sizes, int n_in,
                              void* d_out, int out_size) {
    const float* node_coords   = (const float*)d_in[0];
    const float* node_scores   = (const float*)d_in[1];
    const float* node_features = (const float*)d_in[2];
    const float* node_depths   = (const float*)d_in[3];
    const float* K_left        = (const float*)d_in[4];
    const float* R_left        = (const float*)d_in[5];
    const float* t_init        = (const float*)d_in[6];
    const float* sat_featmap   = (const float*)d_in[7];
    const float* K_sat         = (const float*)d_in[8];
    const float* R_sat         = (const float*)d_in[9];
    const float* t_sat         = (const float*)d_in[10];
    const float* radius        = (const float*)d_in[11];
    int off = (n_in >= 18) ? 0 : -1;
    const float* W_node      = (const float*)d_in[13 + off];
    const float* b_node      = (const float*)d_in[14 + off];
    const float* W_sat       = (const float*)d_in[15 + off];
    const float* b_sat       = (const float*)d_in[16 + off];
    const float* logit_scale = (const float*)d_in[17 + off];
    float* out = (float*)d_out;

    cudaFuncSetAttribute(k_sfmma, cudaFuncAttributeMaxDynamicSharedMemorySize, SMEM_K3);

    k_wcvt<<<128, 256>>>(W_sat);
    k_nf<<<128, 128>>>(node_features, W_node, b_node, node_scores);
    k_pw<<<4, 256>>>(node_coords, node_depths, K_left, R_left, K_sat, R_sat);
    k_sfmma<<<dim3(512, Bv), 256, SMEM_K3>>>(sat_featmap, b_sat);
    k_sample<<<dim3(Sv, Bv), 256>>>(K_sat, R_sat, t_sat, t_init, radius);
    k_final<<<Bv, 256>>>(out, t_init, radius, logit_scale);
}